// round 1
// baseline (speedup 1.0000x reference)
#include <cuda_runtime.h>
#include <math.h>

#define K_ANG 99
#define BB 256
#define TT 2
#define NN 8192
#define TA 16
#define DROP_P (1.0f/64.0f)
#define PI_F 3.14159265358979323846f

__device__ int    g_ok[K_ANG];
__device__ float2 g_cs[BB];

// ---------------- Kernel 1: per-k validity flag ----------------
__global__ void select_kernel(const float* __restrict__ pos,
                              const float* __restrict__ naction,
                              const float* __restrict__ angles_u,
                              const float* __restrict__ drop_u) {
    int k = blockIdx.x;
    int b = threadIdx.x;
    float du = drop_u[k * BB + b];
    float a  = angles_u[(k * BB + b) * 3 + 2] - 0.5f;
    float th = (du < DROP_P ? 0.0f : a) * PI_F;
    float c = cosf(th), s = sinf(th);

    bool ok = true;
    #pragma unroll
    for (int t = 0; t < TT; t++) {
        const float* p = pos + (b * TT + t) * 3;
        float x = p[0], y = p[1], z = p[2];
        float xr = c * x - s * y;
        float yr = s * x + c * y;
        ok = ok && (xr >= -1.0f) && (xr <= 1.0f)
                && (yr >= -1.0f) && (yr <= 1.0f)
                && (z  >= -1.0f) && (z  <= 1.0f);
    }
    #pragma unroll
    for (int t = 0; t < TA; t++) {
        const float* ap = naction + (b * TA + t) * 10;
        float x = ap[0], y = ap[1];
        float xr = c * x - s * y;
        float yr = s * x + c * y;
        ok = ok && (xr >= -1.0f) && (xr <= 1.0f)
                && (yr >= -1.0f) && (yr <= 1.0f);
    }
    int allok = __syncthreads_and(ok ? 1 : 0);
    if (b == 0) g_ok[k] = allok;
}

// ---------------- Kernel 2: pick idx, per-batch cos/sin, small outputs ----------------
__global__ void small_kernel(const float* __restrict__ pos,
                             const float* __restrict__ quat_in,
                             const float* __restrict__ naction,
                             const float* __restrict__ angles_u,
                             const float* __restrict__ drop_u,
                             float* __restrict__ out_pos,
                             float* __restrict__ out_quat,
                             float* __restrict__ out_na) {
    __shared__ int sidx;
    int b = threadIdx.x;
    if (b == 0) {
        int idx = K_ANG - 1;
        for (int k = K_ANG - 1; k >= 0; k--)
            if (g_ok[k]) idx = k;
        sidx = idx;
    }
    __syncthreads();
    int k = sidx;

    float du = drop_u[k * BB + b];
    float a  = angles_u[(k * BB + b) * 3 + 2] - 0.5f;
    float th = (du < DROP_P ? 0.0f : a) * PI_F;
    float c = cosf(th), s = sinf(th);
    g_cs[b] = make_float2(c, s);

    // ---- rotated_pos + rotated_quat ----
    #pragma unroll
    for (int t = 0; t < TT; t++) {
        const float* p = pos + (b * TT + t) * 3;
        float x = p[0], y = p[1], z = p[2];
        out_pos[(b * TT + t) * 3 + 0] = c * x - s * y;
        out_pos[(b * TT + t) * 3 + 1] = s * x + c * y;
        out_pos[(b * TT + t) * 3 + 2] = z;

        // input quat is xyzw; pytorch3d wants wxyz
        const float* q = quat_in + (b * TT + t) * 4;
        float qi = q[0], qj = q[1], qk = q[2], qr = q[3];
        float two_s = 2.0f / (qr * qr + qi * qi + qj * qj + qk * qk);
        float m00 = 1.0f - two_s * (qj * qj + qk * qk);
        float m01 = two_s * (qi * qj - qk * qr);
        float m02 = two_s * (qi * qk + qj * qr);
        float m10 = two_s * (qi * qj + qk * qr);
        float m11 = 1.0f - two_s * (qi * qi + qk * qk);
        float m12 = two_s * (qj * qk - qi * qr);
        float m20 = two_s * (qi * qk - qj * qr);
        float m21 = two_s * (qj * qk + qi * qr);
        float m22 = 1.0f - two_s * (qi * qi + qj * qj);

        // M = Rz(th) @ m
        float n00 = c * m00 - s * m10, n01 = c * m01 - s * m11, n02 = c * m02 - s * m12;
        float n10 = s * m00 + c * m10, n11 = s * m01 + c * m11, n12 = s * m02 + c * m12;
        float n20 = m20, n21 = m21, n22 = m22;

        // matrix_to_quaternion (pytorch3d), first-max tie-break
        float qa[4];
        qa[0] = sqrtf(fmaxf(1.0f + n00 + n11 + n22, 0.0f));
        qa[1] = sqrtf(fmaxf(1.0f + n00 - n11 - n22, 0.0f));
        qa[2] = sqrtf(fmaxf(1.0f - n00 + n11 - n22, 0.0f));
        qa[3] = sqrtf(fmaxf(1.0f - n00 - n11 + n22, 0.0f));
        float cand[4][4] = {
            { qa[0] * qa[0], n21 - n12,     n02 - n20,     n10 - n01     },
            { n21 - n12,     qa[1] * qa[1], n10 + n01,     n02 + n20     },
            { n02 - n20,     n10 + n01,     qa[2] * qa[2], n12 + n21     },
            { n10 - n01,     n20 + n02,     n21 + n12,     qa[3] * qa[3] }
        };
        int best = 0; float bv = qa[0];
        #pragma unroll
        for (int i = 1; i < 4; i++)
            if (qa[i] > bv) { bv = qa[i]; best = i; }
        float d = 2.0f * fmaxf(qa[best], 0.1f);
        float w  = cand[best][0] / d;
        float qx = cand[best][1] / d;
        float qy = cand[best][2] / d;
        float qz = cand[best][3] / d;
        float* oq = out_quat + (b * TT + t) * 4;
        oq[0] = qx; oq[1] = qy; oq[2] = qz; oq[3] = w;   // back to xyzw
    }

    // ---- rotated_naction ----
    #pragma unroll
    for (int t = 0; t < TA; t++) {
        const float* na = naction + (b * TA + t) * 10;
        float x = na[0], y = na[1], z = na[2];
        float a1x = na[3], a1y = na[4], a1z = na[5];
        float a2x = na[6], a2y = na[7], a2z = na[8];
        float g = na[9];

        float n1 = sqrtf(a1x * a1x + a1y * a1y + a1z * a1z);
        float b1x = a1x / n1, b1y = a1y / n1, b1z = a1z / n1;
        float dp = b1x * a2x + b1y * a2y + b1z * a2z;
        float b2x = a2x - dp * b1x, b2y = a2y - dp * b1y, b2z = a2z - dp * b1z;
        float n2 = sqrtf(b2x * b2x + b2y * b2y + b2z * b2z);
        b2x /= n2; b2y /= n2; b2z /= n2;

        // (Rz @ M) first two rows; row3 (cross) not needed for 6d output
        float r0x = c * b1x - s * b2x, r0y = c * b1y - s * b2y, r0z = c * b1z - s * b2z;
        float r1x = s * b1x + c * b2x, r1y = s * b1y + c * b2y, r1z = s * b1z + c * b2z;

        float* o = out_na + (b * TA + t) * 10;
        o[0] = c * x - s * y;
        o[1] = s * x + c * y;
        o[2] = z;
        o[3] = r0x; o[4] = r0y; o[5] = r0z;
        o[6] = r1x; o[7] = r1y; o[8] = r1z;
        o[9] = g;
    }
}

// ---------------- Kernel 3: streaming point-cloud rotation ----------------
// Each thread handles 2 consecutive points (48B = 3 x float4), fully coalesced.
__global__ void pc_kernel(const float4* __restrict__ pc, float4* __restrict__ out) {
    int p = blockIdx.x * blockDim.x + threadIdx.x;   // pair index, 2 points per pair
    int b = p >> 13;                                  // (p*2) / (T*N=16384)
    float2 cs = g_cs[b];
    float c = cs.x, s = cs.y;

    const float4* ip = pc + (size_t)p * 3;
    float4 f0 = ip[0];
    float4 f1 = ip[1];
    float4 f2 = ip[2];

    // point 0: xyz = f0.x,f0.y,f0.z ; features f0.w,f1.x,f1.y
    float x0 = f0.x, y0 = f0.y;
    f0.x = c * x0 - s * y0;
    f0.y = s * x0 + c * y0;
    // point 1: xyz = f1.z,f1.w,f2.x ; features f2.y,f2.z,f2.w
    float x1 = f1.z, y1 = f1.w;
    f1.z = c * x1 - s * y1;
    f1.w = s * x1 + c * y1;

    float4* op = out + (size_t)p * 3;
    op[0] = f0;
    op[1] = f1;
    op[2] = f2;
}

extern "C" void kernel_launch(void* const* d_in, const int* in_sizes, int n_in,
                              void* d_out, int out_size) {
    const float* pc    = (const float*)d_in[0];  // (256,2,8192,6)
    const float* pos   = (const float*)d_in[1];  // (256,2,3)
    const float* quat  = (const float*)d_in[2];  // (256,2,4) xyzw
    const float* na    = (const float*)d_in[3];  // (256,16,10)
    const float* ang   = (const float*)d_in[4];  // (99,256,3)
    const float* drop  = (const float*)d_in[5];  // (99,256)

    float* out      = (float*)d_out;
    float* out_pc   = out;                                    // 25,165,824
    float* out_pos  = out_pc  + (size_t)BB * TT * NN * 6;     // 1,536
    float* out_quat = out_pos + BB * TT * 3;                  // 2,048
    float* out_na   = out_quat + BB * TT * 4;                 // 40,960

    select_kernel<<<K_ANG, BB>>>(pos, na, ang, drop);
    small_kernel<<<1, BB>>>(pos, quat, na, ang, drop, out_pos, out_quat, out_na);

    int pairs = BB * TT * NN / 2;                 // 2,097,152
    pc_kernel<<<pairs / 256, 256>>>((const float4*)pc, (float4*)out_pc);
}

// round 2
// speedup vs baseline: 1.8325x; 1.8325x over previous
#include <cuda_runtime.h>
#include <math.h>

#define K_ANG 99
#define BB 256
#define TT 2
#define NN 8192
#define TA 16
#define NPTS 18              // 2 eef-pos + 16 action-pos xy points per batch
#define DROP_P (1.0f/64.0f)
#define PI_F 3.14159265358979323846f

__device__ int    g_ok[K_ANG];
__device__ int    g_easyAll;
__device__ int    g_zok[BB];
__device__ float2 g_xy[BB][NPTS];

// ---------- helper: theta -> (c,s) for batch b given chosen idx ----------
__device__ __forceinline__ float2 get_cs(int b,
                                         const float* __restrict__ drop_u,
                                         const float* __restrict__ angles_u) {
    int idx;
    if (g_easyAll) {
        idx = 0;                       // all k valid -> argmax(ok) = 0
    } else {
        idx = K_ANG - 1;
        for (int k = 0; k < K_ANG; k++)
            if (g_ok[k]) { idx = k; break; }
    }
    float du = drop_u[idx * BB + b];
    float a  = angles_u[(idx * BB + b) * 3 + 2] - 0.5f;
    float th = (du < DROP_P ? 0.0f : a) * PI_F;
    float s, c;
    sincosf(th, &s, &c);
    return make_float2(c, s);
}

// ---------------- Kernel 1: prep (per-b easy flag + compact xy buffer) ----------------
// Rz preserves xy-norm: if hypot(x,y) <= 1 for all points and |z|<=1 for eef-pos,
// the bounds check passes for EVERY theta -> selection is trivially k=0.
__global__ void prep_kernel(const float* __restrict__ pos,
                            const float* __restrict__ naction) {
    int b = threadIdx.x;
    float r2max = 0.0f;
    bool zok = true;
    #pragma unroll
    for (int t = 0; t < TT; t++) {
        const float* p = pos + (b * TT + t) * 3;
        float x = p[0], y = p[1], z = p[2];
        r2max = fmaxf(r2max, x * x + y * y);
        zok = zok && (z >= -1.0f) && (z <= 1.0f);
        g_xy[b][t] = make_float2(x, y);
    }
    #pragma unroll
    for (int t = 0; t < TA; t++) {
        const float* ap = naction + (b * TA + t) * 10;
        float x = ap[0], y = ap[1];
        r2max = fmaxf(r2max, x * x + y * y);
        g_xy[b][TT + t] = make_float2(x, y);
    }
    g_zok[b] = zok ? 1 : 0;
    int easy = (r2max <= 1.0f && zok) ? 1 : 0;
    int all = __syncthreads_and(easy);
    if (b == 0) g_easyAll = all;
}

// ---------------- Kernel 2: per-k validity (slow path only) ----------------
__global__ void select_kernel(const float* __restrict__ angles_u,
                              const float* __restrict__ drop_u) {
    if (g_easyAll) return;             // uniform read -> whole grid exits; g_ok unread
    int k = blockIdx.x;
    int b = threadIdx.x;
    float du = drop_u[k * BB + b];
    float a  = angles_u[(k * BB + b) * 3 + 2] - 0.5f;
    float th = (du < DROP_P ? 0.0f : a) * PI_F;
    float s, c;
    sincosf(th, &s, &c);

    bool ok = (g_zok[b] != 0);
    #pragma unroll
    for (int i = 0; i < NPTS; i++) {
        float2 p = g_xy[b][i];
        float xr = c * p.x - s * p.y;
        float yr = s * p.x + c * p.y;
        ok = ok && (xr >= -1.0f) && (xr <= 1.0f)
                && (yr >= -1.0f) && (yr <= 1.0f);
    }
    int allok = __syncthreads_and(ok ? 1 : 0);
    if (b == 0) g_ok[k] = allok;
}

// ---------------- Kernel 3: small outputs, one thread per (b,t) task ----------------
// Tasks: T in [0,512)        -> pos+quat for (b=T>>1, t=T&1)
//        T in [512,512+4096) -> naction for (b=(T-512)>>4, t=(T-512)&15)
__global__ void small_kernel(const float* __restrict__ pos,
                             const float* __restrict__ quat_in,
                             const float* __restrict__ naction,
                             const float* __restrict__ angles_u,
                             const float* __restrict__ drop_u,
                             float* __restrict__ out_pos,
                             float* __restrict__ out_quat,
                             float* __restrict__ out_na) {
    int T = blockIdx.x * blockDim.x + threadIdx.x;

    if (T < BB * TT) {
        int b = T >> 1, t = T & 1;
        float2 cs = get_cs(b, drop_u, angles_u);
        float c = cs.x, s = cs.y;

        const float* p = pos + (b * TT + t) * 3;
        float x = p[0], y = p[1], z = p[2];
        out_pos[(b * TT + t) * 3 + 0] = c * x - s * y;
        out_pos[(b * TT + t) * 3 + 1] = s * x + c * y;
        out_pos[(b * TT + t) * 3 + 2] = z;

        // input quat xyzw; pytorch3d math in wxyz
        const float* q = quat_in + (b * TT + t) * 4;
        float qi = q[0], qj = q[1], qk = q[2], qr = q[3];
        float two_s = 2.0f / (qr * qr + qi * qi + qj * qj + qk * qk);
        float m00 = 1.0f - two_s * (qj * qj + qk * qk);
        float m01 = two_s * (qi * qj - qk * qr);
        float m02 = two_s * (qi * qk + qj * qr);
        float m10 = two_s * (qi * qj + qk * qr);
        float m11 = 1.0f - two_s * (qi * qi + qk * qk);
        float m12 = two_s * (qj * qk - qi * qr);
        float m20 = two_s * (qi * qk - qj * qr);
        float m21 = two_s * (qj * qk + qi * qr);
        float m22 = 1.0f - two_s * (qi * qi + qj * qj);

        // M = Rz(th) @ m
        float n00 = c * m00 - s * m10, n01 = c * m01 - s * m11, n02 = c * m02 - s * m12;
        float n10 = s * m00 + c * m10, n11 = s * m01 + c * m11, n12 = s * m02 + c * m12;
        float n20 = m20, n21 = m21, n22 = m22;

        // matrix_to_quaternion, first-max tie-break, no local-array spill
        float qa0 = sqrtf(fmaxf(1.0f + n00 + n11 + n22, 0.0f));
        float qa1 = sqrtf(fmaxf(1.0f + n00 - n11 - n22, 0.0f));
        float qa2 = sqrtf(fmaxf(1.0f - n00 + n11 - n22, 0.0f));
        float qa3 = sqrtf(fmaxf(1.0f - n00 - n11 + n22, 0.0f));
        int best = 0; float bv = qa0, qbest = qa0;
        if (qa1 > bv) { bv = qa1; best = 1; qbest = qa1; }
        if (qa2 > bv) { bv = qa2; best = 2; qbest = qa2; }
        if (qa3 > bv) { bv = qa3; best = 3; qbest = qa3; }
        float cw, cx, cy, cz;
        if (best == 0)      { cw = qa0 * qa0; cx = n21 - n12;  cy = n02 - n20;  cz = n10 - n01; }
        else if (best == 1) { cw = n21 - n12; cx = qa1 * qa1;  cy = n10 + n01;  cz = n02 + n20; }
        else if (best == 2) { cw = n02 - n20; cx = n10 + n01;  cy = qa2 * qa2;  cz = n12 + n21; }
        else                { cw = n10 - n01; cx = n20 + n02;  cy = n21 + n12;  cz = qa3 * qa3; }
        float d = 2.0f * fmaxf(qbest, 0.1f);
        float* oq = out_quat + (b * TT + t) * 4;
        oq[0] = cx / d; oq[1] = cy / d; oq[2] = cz / d; oq[3] = cw / d;  // back to xyzw
        return;
    }

    int i = T - BB * TT;
    if (i < BB * TA) {
        int b = i >> 4, t = i & 15;
        float2 cs = get_cs(b, drop_u, angles_u);
        float c = cs.x, s = cs.y;

        const float* na = naction + (b * TA + t) * 10;
        float x = na[0], y = na[1], z = na[2];
        float a1x = na[3], a1y = na[4], a1z = na[5];
        float a2x = na[6], a2y = na[7], a2z = na[8];
        float g = na[9];

        float n1 = sqrtf(a1x * a1x + a1y * a1y + a1z * a1z);
        float b1x = a1x / n1, b1y = a1y / n1, b1z = a1z / n1;
        float dp = b1x * a2x + b1y * a2y + b1z * a2z;
        float b2x = a2x - dp * b1x, b2y = a2y - dp * b1y, b2z = a2z - dp * b1z;
        float n2 = sqrtf(b2x * b2x + b2y * b2y + b2z * b2z);
        b2x /= n2; b2y /= n2; b2z /= n2;

        float* o = out_na + (b * TA + t) * 10;
        o[0] = c * x - s * y;
        o[1] = s * x + c * y;
        o[2] = z;
        o[3] = c * b1x - s * b2x; o[4] = c * b1y - s * b2y; o[5] = c * b1z - s * b2z;
        o[6] = s * b1x + c * b2x; o[7] = s * b1y + c * b2y; o[8] = s * b1z + c * b2z;
        o[9] = g;
    }
}

// ---------------- Kernel 4: streaming point-cloud rotation ----------------
// 4 points per thread = 6 x float4 = 96B; MLP_p1 = 6; evict-first hints.
__global__ void pc_kernel(const float4* __restrict__ pc,
                          float4* __restrict__ out,
                          const float* __restrict__ angles_u,
                          const float* __restrict__ drop_u) {
    int q = blockIdx.x * blockDim.x + threadIdx.x;   // quad index (4 points)
    const float4* ip = pc + (size_t)q * 6;

    // issue all loads first — DRAM latency overlaps the c/s prologue below
    float4 f0 = __ldcs(ip + 0);
    float4 f1 = __ldcs(ip + 1);
    float4 f2 = __ldcs(ip + 2);
    float4 f3 = __ldcs(ip + 3);
    float4 f4 = __ldcs(ip + 4);
    float4 f5 = __ldcs(ip + 5);

    __shared__ float2 cs_sh;
    if (threadIdx.x == 0) {
        int b = q >> 12;                 // 4096 quads per batch; uniform per block
        cs_sh = get_cs(b, drop_u, angles_u);
    }
    __syncthreads();
    float c = cs_sh.x, s = cs_sh.y;

    // point layout (6 floats each): p0=f0.xyzw,f1.xy  p1=f1.zw,f2.xyzw
    //                               p2=f3.xyzw,f4.xy  p3=f4.zw,f5.xyzw
    float x, y;
    x = f0.x; y = f0.y; f0.x = c * x - s * y; f0.y = s * x + c * y;
    x = f1.z; y = f1.w; f1.z = c * x - s * y; f1.w = s * x + c * y;
    x = f3.x; y = f3.y; f3.x = c * x - s * y; f3.y = s * x + c * y;
    x = f4.z; y = f4.w; f4.z = c * x - s * y; f4.w = s * x + c * y;

    float4* op = out + (size_t)q * 6;
    __stcs(op + 0, f0);
    __stcs(op + 1, f1);
    __stcs(op + 2, f2);
    __stcs(op + 3, f3);
    __stcs(op + 4, f4);
    __stcs(op + 5, f5);
}

extern "C" void kernel_launch(void* const* d_in, const int* in_sizes, int n_in,
                              void* d_out, int out_size) {
    const float* pc    = (const float*)d_in[0];  // (256,2,8192,6)
    const float* pos   = (const float*)d_in[1];  // (256,2,3)
    const float* quat  = (const float*)d_in[2];  // (256,2,4) xyzw
    const float* na    = (const float*)d_in[3];  // (256,16,10)
    const float* ang   = (const float*)d_in[4];  // (99,256,3)
    const float* drop  = (const float*)d_in[5];  // (99,256)

    float* out      = (float*)d_out;
    float* out_pc   = out;
    float* out_pos  = out_pc  + (size_t)BB * TT * NN * 6;
    float* out_quat = out_pos + BB * TT * 3;
    float* out_na   = out_quat + BB * TT * 4;

    prep_kernel<<<1, BB>>>(pos, na);
    select_kernel<<<K_ANG, BB>>>(ang, drop);
    small_kernel<<<18, 256>>>(pos, quat, na, ang, drop, out_pos, out_quat, out_na);

    int quads = BB * TT * NN / 4;                  // 1,048,576
    pc_kernel<<<quads / 256, 256>>>((const float4*)pc, (float4*)out_pc, ang, drop);
}